// round 10
// baseline (speedup 1.0000x reference)
#include <cuda_runtime.h>
#include <cuda_fp16.h>
#include <cstdint>

// Problem constants
#define BB 16384
#define TT 10
#define II 184
#define HH 128
#define GG 512            // 4*H
#define MM (BB*TT)        // 163840 rows for xproj GEMMs
#define K1P 192           // layer-1 K padded (184 -> 192)
#define K2P 256           // layer-2 K

// ---------------- device scratch (no allocations allowed) ----------------
__device__ float g_xpf[(size_t)MM * GG];
__device__ float g_xpb[(size_t)MM * GG];
__device__ float g_o2 [(size_t)MM * 2 * HH];
__device__ __half g_xhi[(size_t)MM * K1P];          // x split hi (fp16)
__device__ __half g_xlo[(size_t)MM * K1P];          // x split lo
__device__ __half g_ohi[(size_t)MM * K2P];          // layer1 out split hi
__device__ __half g_olo[(size_t)MM * K2P];          // layer1 out split lo
__device__ __half g_whi[4 * (size_t)GG * K2P];      // w_ih hi only (4 slots)
__device__ __half g_whhhi[4 * (size_t)GG * HH];     // w_hh hi only (4 slots)

// ---------------- small PTX helpers ----------------
__device__ __forceinline__ uint32_t smem_u32(const void* p) {
    uint32_t a;
    asm("{ .reg .u64 t; cvta.to.shared.u64 t, %1; cvt.u32.u64 %0, t; }" : "=r"(a) : "l"(p));
    return a;
}
__device__ __forceinline__ void ldm_x4(uint32_t& r0, uint32_t& r1, uint32_t& r2, uint32_t& r3,
                                       uint32_t addr) {
    asm volatile("ldmatrix.sync.aligned.m8n8.x4.shared.b16 {%0,%1,%2,%3}, [%4];"
                 : "=r"(r0), "=r"(r1), "=r"(r2), "=r"(r3) : "r"(addr));
}
__device__ __forceinline__ void mma_f16(float* c, const uint32_t* a, const uint32_t* b) {
    asm volatile(
        "mma.sync.aligned.m16n8k16.row.col.f32.f16.f16.f32 "
        "{%0,%1,%2,%3}, {%4,%5,%6,%7}, {%8,%9}, {%0,%1,%2,%3};"
        : "+f"(c[0]), "+f"(c[1]), "+f"(c[2]), "+f"(c[3])
        : "r"(a[0]), "r"(a[1]), "r"(a[2]), "r"(a[3]), "r"(b[0]), "r"(b[1]));
}
__device__ __forceinline__ void cp16(uint32_t dst, const void* src) {
    asm volatile("cp.async.cg.shared.global [%0], [%1], 16;" :: "r"(dst), "l"(src));
}
__device__ __forceinline__ void cp_commit() {
    asm volatile("cp.async.commit_group;" ::: "memory");
}
__device__ __forceinline__ void cp_wait1() {
    asm volatile("cp.async.wait_group 1;" ::: "memory");
}
__device__ __forceinline__ void cp_wait0() {
    asm volatile("cp.async.wait_group 0;" ::: "memory");
}

// ---------------- activation helpers ----------------
__device__ __forceinline__ float fsig(float x) {
    return __fdividef(1.0f, 1.0f + __expf(-x));
}
__device__ __forceinline__ float ftanh(float x) {
    x = fminf(x, 15.0f);
    float e = __expf(2.0f * x);
    return __fdividef(e - 1.0f, e + 1.0f);
}

// ---------------- fp32 -> fp16 hi/lo split (with K zero-padding) ----------
__global__ void convert_split(const float* __restrict__ src,
                              __half* __restrict__ dhi,
                              __half* __restrict__ dlo,
                              unsigned rows, unsigned Ksrc, unsigned Kpad)
{
    unsigned total = rows * Kpad;
    for (unsigned idx = blockIdx.x * blockDim.x + threadIdx.x; idx < total;
         idx += gridDim.x * blockDim.x) {
        unsigned row = idx / Kpad;
        unsigned k = idx - row * Kpad;
        float v = (k < Ksrc) ? src[(size_t)row * Ksrc + k] : 0.0f;
        __half h = __float2half_rn(v);
        dhi[idx] = h;
        dlo[idx] = __float2half_rn(v - __half2float(h));
    }
}

// ---------------- fp32 -> fp16 hi only (weights) --------------------------
__global__ void convert_h(const float* __restrict__ src,
                          __half* __restrict__ dhi,
                          unsigned rows, unsigned Ksrc, unsigned Kpad)
{
    unsigned total = rows * Kpad;
    for (unsigned idx = blockIdx.x * blockDim.x + threadIdx.x; idx < total;
         idx += gridDim.x * blockDim.x) {
        unsigned row = idx / Kpad;
        unsigned k = idx - row * Kpad;
        float v = (k < Ksrc) ? src[(size_t)row * Ksrc + k] : 0.0f;
        dhi[idx] = __float2half_rn(v);
    }
}

// ---------------- split-fp16 2-term GEMM, cp.async 2-stage pipeline -------
// CTA tile 128x64 (32 accs/thread -> ~100 regs natural, so the (256,2)
// occupancy cap does NOT spill; 2 CTAs/SM cover sync bubbles).
// FUSED f+b: grid = (16, M/128). blockIdx.x>>3 = direction, &7 = N block.
#define PIT 72
#define PITB 144
#define ATILEB (128 * PITB)            // 18432 bytes (A operand tile)
#define BTILEB (64 * PITB)             // 9216 bytes (B operand tile, 64 rows)
#define GSTAGEB (2 * ATILEB + BTILEB)  // 46080 bytes per pipeline stage
#define GEMMSMEM (2 * GSTAGEB + 256)   // 92416
__global__ __launch_bounds__(256, 2) void gemm_mma(
    const __half* __restrict__ a_hi, const __half* __restrict__ a_lo,
    const __half* __restrict__ w_base,          // 2 slots, stride GG*Kpad
    int Kpad, int nchunks,
    const float* __restrict__ b1f, const float* __restrict__ b2f,
    const float* __restrict__ b1b, const float* __restrict__ b2b,
    float* __restrict__ Cf, float* __restrict__ Cb)
{
    extern __shared__ __half sm[];
    const uint32_t sb0 = smem_u32(sm);
    float* sbias = (float*)((char*)sm + 2 * GSTAGEB);

    const int tid  = threadIdx.x;
    const int wid  = tid >> 5;
    const int lane = tid & 31;
    const int wm   = wid & 3;                    // 4 M groups of 32
    const int wn   = wid >> 2;                   // 2 N groups of 32
    const int dsel = blockIdx.x >> 3;            // 0 = fwd, 1 = bwd
    const int n0   = (blockIdx.x & 7) * 64;      // N block
    const int m0   = blockIdx.y * 128;

    const __half* w_hi = w_base + (size_t)dsel * GG * Kpad;
    const float*  b1   = dsel ? b1b : b1f;
    const float*  b2   = dsel ? b2b : b2f;
    float*        C    = dsel ? Cb  : Cf;

    if (tid < 64) sbias[tid] = b1[n0 + tid] + b2[n0 + tid];

    const uint32_t aoff = (uint32_t)(lane & 15) * PITB + (uint32_t)(lane >> 4) * 16;
    const uint32_t boff = ((uint32_t)((lane & 7) + ((lane >> 4) << 3))) * PITB
                        + (uint32_t)((lane >> 3) & 1) * 16;

    // issue cp.async for chunk c into stage st (Ahi 128r, Alo 128r, B 64r)
    auto load_chunk = [&](int c, int st) {
        const int kb = c * 64;
        const uint32_t base = sb0 + (uint32_t)st * GSTAGEB;
#pragma unroll
        for (int i = 0; i < 4; i++) {
            int idx = tid + i * 256;          // 0..1023
            int row = idx >> 3, seg = idx & 7;
            uint32_t d = base + (uint32_t)row * PITB + (uint32_t)seg * 16;
            cp16(d,          a_hi + (size_t)(m0 + row) * Kpad + kb + seg * 8);
            cp16(d + ATILEB, a_lo + (size_t)(m0 + row) * Kpad + kb + seg * 8);
        }
#pragma unroll
        for (int i = 0; i < 2; i++) {
            int idx = tid + i * 256;          // 0..511
            int row = idx >> 3, seg = idx & 7;
            cp16(base + 2 * ATILEB + (uint32_t)row * PITB + (uint32_t)seg * 16,
                 w_hi + (size_t)(n0 + row) * Kpad + kb + seg * 8);
        }
        cp_commit();
    };

    float acc[2][4][4];
#pragma unroll
    for (int mt = 0; mt < 2; mt++)
#pragma unroll
        for (int nt = 0; nt < 4; nt++)
#pragma unroll
            for (int q = 0; q < 4; q++) acc[mt][nt][q] = 0.0f;

    load_chunk(0, 0);
    if (nchunks > 1) load_chunk(1, 1);

    for (int c = 0; c < nchunks; c++) {
        if (c < nchunks - 1) cp_wait1(); else cp_wait0();
        __syncthreads();

        const uint32_t stg = sb0 + (uint32_t)(c & 1) * GSTAGEB;
        const uint32_t sAh = stg, sAl = stg + ATILEB, sBh = stg + 2 * ATILEB;

#pragma unroll
        for (int ks = 0; ks < 4; ks++) {
            const uint32_t kbyte = (uint32_t)(ks * 32);

            uint32_t ah[2][4], al[2][4];
#pragma unroll
            for (int mt = 0; mt < 2; mt++) {
                uint32_t rbase = (uint32_t)(wm * 32 + mt * 16) * PITB + aoff + kbyte;
                ldm_x4(ah[mt][0], ah[mt][1], ah[mt][2], ah[mt][3], sAh + rbase);
                ldm_x4(al[mt][0], al[mt][1], al[mt][2], al[mt][3], sAl + rbase);
            }

            uint32_t bh[4][2];
#pragma unroll
            for (int p = 0; p < 2; p++) {
                uint32_t nb = (uint32_t)(wn * 32 + p * 16) * PITB + boff + kbyte;
                ldm_x4(bh[2*p][0], bh[2*p][1], bh[2*p+1][0], bh[2*p+1][1], sBh + nb);
            }
#pragma unroll
            for (int mt = 0; mt < 2; mt++)
#pragma unroll
                for (int nt = 0; nt < 4; nt++) {
                    float* cc = acc[mt][nt];
                    mma_f16(cc, ah[mt], bh[nt]);   // hi * Whi
                    mma_f16(cc, al[mt], bh[nt]);   // lo * Whi
                }
        }
        __syncthreads();
        if (c + 2 < nchunks) load_chunk(c + 2, c & 1);
    }

    const int g = lane >> 2, t = lane & 3;
#pragma unroll
    for (int mt = 0; mt < 2; mt++) {
        const int row0 = m0 + wm * 32 + mt * 16 + g;
#pragma unroll
        for (int nt = 0; nt < 4; nt++) {
            const int cl = wn * 32 + nt * 8 + 2 * t;
            float2 v0, v1;
            v0.x = acc[mt][nt][0] + sbias[cl];
            v0.y = acc[mt][nt][1] + sbias[cl + 1];
            v1.x = acc[mt][nt][2] + sbias[cl];
            v1.y = acc[mt][nt][3] + sbias[cl + 1];
            *(float2*)&C[(size_t)row0 * GG + n0 + cl] = v0;
            *(float2*)&C[(size_t)(row0 + 8) * GG + n0 + cl] = v1;
        }
    }
}

// ---------------- tensorized bidirectional LSTM recurrence ----------------
// 64 batch rows/CTA, 1 direction. Full W_hh (hi fp16) resident in SMEM.
// h kept HI-ONLY in smem (recurrent term is the minor gate contribution, so
// fp16 h adds only ~7e-5 abs error) -> half the MMAs/ldmatrix of R7.
// gmem ohi/olo (layer-2 GEMM A operand) still written as exact hi/lo.
#define HPITB 272                         // smem row pitch bytes (136 halves)
#define WREGB (512 * HPITB)               // 139264 bytes: whole W_hh hi
#define RECSMEM (WREGB + 64 * HPITB)      // +17408 = 156672
__global__ __launch_bounds__(256, 1) void lstm_rec_mma(
    const float* __restrict__ xp_f, const float* __restrict__ xp_b,
    const __half* __restrict__ whh_hi_base,   // 2 dirs, each [512][128]
    float* __restrict__ out32,
    __half* __restrict__ ohi, __half* __restrict__ olo)
{
    extern __shared__ __half smr[];
    const uint32_t sb = smem_u32(smr);
    const uint32_t wB  = sb;
    const uint32_t hHi = sb + WREGB;

    const int dir = blockIdx.y;
    const float* xp = dir ? xp_b : xp_f;
    const __half* whh_hi = whh_hi_base + (size_t)dir * GG * HH;

    const int tid  = threadIdx.x;
    const int wid  = tid >> 5;
    const int lane = tid & 31;
    const int wm   = wid & 1;        // M half (32 rows)
    const int wn   = wid >> 1;       // 0..3 -> hidden col group of 32
    const int b0   = blockIdx.x * 64;
    const int g4   = lane >> 2;
    const int t4   = lane & 3;

    const uint32_t aoff = (uint32_t)(lane & 15) * HPITB + (uint32_t)(lane >> 4) * 16;
    const uint32_t boff = ((uint32_t)((lane & 7) + ((lane >> 4) << 3))) * HPITB
                        + (uint32_t)((lane >> 3) & 1) * 16;

    // load the ENTIRE W_hh (hi) once: 512 rows x 256B -> 8192 cp16
#pragma unroll
    for (int i = 0; i < 32; i++) {
        int idx = tid + i * 256;            // 0..8191
        int row = idx >> 4, seg = idx & 15;
        cp16(wB + (uint32_t)row * HPITB + (uint32_t)seg * 16,
             whh_hi + (size_t)row * HH + seg * 8);
    }
    cp_commit();

    // zero h (hi only, 64*272 bytes)
    for (int i = tid; i < (64 * HPITB) / 4; i += 256)
        *(uint32_t*)((char*)smr + WREGB + i * 4) = 0u;
    cp_wait0();
    __syncthreads();

    float cst[2][4][4];
#pragma unroll
    for (int mt = 0; mt < 2; mt++)
#pragma unroll
        for (int nt = 0; nt < 4; nt++)
#pragma unroll
            for (int e = 0; e < 4; e++) cst[mt][nt][e] = 0.0f;

    float acc[4][2][4][4];

    for (int s = 0; s < TT; s++) {
        const int t = dir ? (TT - 1 - s) : s;

        // init accumulators from xproj (biases pre-folded by GEMM epilogue)
#pragma unroll
        for (int gate = 0; gate < 4; gate++)
#pragma unroll
            for (int mt = 0; mt < 2; mt++) {
                const int r = wm * 32 + mt * 16 + g4;
                const size_t base0 = ((size_t)(b0 + r) * TT + t) * GG + gate * 128;
                const size_t base1 = ((size_t)(b0 + r + 8) * TT + t) * GG + gate * 128;
#pragma unroll
                for (int nt = 0; nt < 4; nt++) {
                    const int j = wn * 32 + nt * 8 + 2 * t4;
                    float2 v0 = *(const float2*)&xp[base0 + j];
                    float2 v1 = *(const float2*)&xp[base1 + j];
                    acc[gate][mt][nt][0] = v0.x; acc[gate][mt][nt][1] = v0.y;
                    acc[gate][mt][nt][2] = v1.x; acc[gate][mt][nt][3] = v1.y;
                }
            }

        // gates += h_prev @ W_hh^T (h hi only)
#pragma unroll
        for (int ks = 0; ks < 8; ks++) {
            const uint32_t kb = (uint32_t)(ks * 32);
            uint32_t ah[2][4];
#pragma unroll
            for (int mt = 0; mt < 2; mt++) {
                uint32_t rb = (uint32_t)(wm * 32 + mt * 16) * HPITB + aoff + kb;
                ldm_x4(ah[mt][0], ah[mt][1], ah[mt][2], ah[mt][3], hHi + rb);
            }
#pragma unroll
            for (int gate = 0; gate < 4; gate++) {
                uint32_t bh[4][2];
#pragma unroll
                for (int p = 0; p < 2; p++) {
                    uint32_t nb = (uint32_t)(gate * 128 + wn * 32 + p * 16) * HPITB + boff + kb;
                    ldm_x4(bh[2*p][0], bh[2*p][1], bh[2*p+1][0], bh[2*p+1][1], wB + nb);
                }
#pragma unroll
                for (int mt = 0; mt < 2; mt++)
#pragma unroll
                    for (int nt = 0; nt < 4; nt++)
                        mma_f16(acc[gate][mt][nt], ah[mt], bh[nt]);
            }
        }
        __syncthreads();   // all h reads complete before overwrite

        // activations + cell update + h emit
#pragma unroll
        for (int mt = 0; mt < 2; mt++) {
            const int r = wm * 32 + mt * 16 + g4;
#pragma unroll
            for (int nt = 0; nt < 4; nt++) {
                const int j = wn * 32 + nt * 8 + 2 * t4;
                float hv[4];
#pragma unroll
                for (int e = 0; e < 4; e++) {
                    float ig = fsig(acc[0][mt][nt][e]);
                    float fg = fsig(acc[1][mt][nt][e]);
                    float gg = ftanh(acc[2][mt][nt][e]);
                    float og = fsig(acc[3][mt][nt][e]);
                    float cc = fg * cst[mt][nt][e] + ig * gg;
                    cst[mt][nt][e] = cc;
                    hv[e] = og * ftanh(cc);
                }
                __half h0x = __float2half_rn(hv[0]);
                __half h0y = __float2half_rn(hv[1]);
                __half h1x = __float2half_rn(hv[2]);
                __half h1y = __float2half_rn(hv[3]);
                __half2 hp0 = __halves2half2(h0x, h0y);
                __half2 hp1 = __halves2half2(h1x, h1y);
                uint32_t uh0 = *reinterpret_cast<uint32_t*>(&hp0);
                uint32_t uh1 = *reinterpret_cast<uint32_t*>(&hp1);

                // smem h (hi only) for next step
                *(uint32_t*)((char*)smr + WREGB + r * HPITB + j * 2) = uh0;
                *(uint32_t*)((char*)smr + WREGB + (r + 8) * HPITB + j * 2) = uh1;

                // gmem output
                const size_t ob0 = ((size_t)(b0 + r) * TT + t) * (2 * HH) + dir * HH + j;
                const size_t ob1 = ((size_t)(b0 + r + 8) * TT + t) * (2 * HH) + dir * HH + j;
                if (out32) {
                    *(float2*)&out32[ob0] = make_float2(hv[0], hv[1]);
                    *(float2*)&out32[ob1] = make_float2(hv[2], hv[3]);
                } else {
                    __half2 lp0 = __halves2half2(__float2half_rn(hv[0] - __half2float(h0x)),
                                                 __float2half_rn(hv[1] - __half2float(h0y)));
                    __half2 lp1 = __halves2half2(__float2half_rn(hv[2] - __half2float(h1x)),
                                                 __float2half_rn(hv[3] - __half2float(h1y)));
                    *(uint32_t*)&ohi[ob0] = uh0;
                    *(uint32_t*)&ohi[ob1] = uh1;
                    *(uint32_t*)&olo[ob0] = *reinterpret_cast<uint32_t*>(&lp0);
                    *(uint32_t*)&olo[ob1] = *reinterpret_cast<uint32_t*>(&lp1);
                }
            }
        }
        __syncthreads();   // h writes visible before next step's reads
    }
}

// ---------------- fused maxpool(T) + FC(512->64) + ReLU + FC(64->1) -------
#define W1PITCH 517
__global__ __launch_bounds__(256) void pool_fc(
    const float* __restrict__ o2,
    const float* __restrict__ fc1w, const float* __restrict__ fc1b,
    const float* __restrict__ fc2w, const float* __restrict__ fc2b,
    float* __restrict__ y, int rows_per_warp)
{
    extern __shared__ float smf[];
    float* w1    = smf;
    float* feats = smf + 64 * W1PITCH;

    for (int i = threadIdx.x; i < 64 * 512; i += 256) {
        int j = i >> 9, f = i & 511;
        w1[j * W1PITCH + f] = fc1w[i];
    }
    __syncthreads();

    const int wid  = threadIdx.x >> 5;
    const int lane = threadIdx.x & 31;
    float* myfeat = feats + wid * 512;

    for (int it = 0; it < rows_per_warp; it++) {
        int b = blockIdx.x * (8 * rows_per_warp) + it * 8 + wid;

#pragma unroll
        for (int q = 0; q < 8; q++) {
            int cc = lane + q * 32;
            float m0 = -3.4e38f, m1 = -3.4e38f;
#pragma unroll
            for (int t = 0; t < 5; t++)
                m0 = fmaxf(m0, o2[((size_t)b * TT + t) * (2 * HH) + cc]);
#pragma unroll
            for (int t = 5; t < 10; t++)
                m1 = fmaxf(m1, o2[((size_t)b * TT + t) * (2 * HH) + cc]);
            myfeat[cc * 2 + 0] = m0;
            myfeat[cc * 2 + 1] = m1;
        }
        __syncwarp();

        float a0 = fc1b[lane];
        float a1 = fc1b[lane + 32];
        const float* wr0 = &w1[lane * W1PITCH];
        const float* wr1 = &w1[(lane + 32) * W1PITCH];
#pragma unroll 8
        for (int f = 0; f < 512; f++) {
            float v = myfeat[f];
            a0 += v * wr0[f];
            a1 += v * wr1[f];
        }
        a0 = fmaxf(a0, 0.0f);
        a1 = fmaxf(a1, 0.0f);

        float p = a0 * fc2w[lane] + a1 * fc2w[lane + 32];
#pragma unroll
        for (int off = 16; off; off >>= 1)
            p += __shfl_down_sync(0xffffffffu, p, off);
        if (lane == 0) y[b] = p + fc2b[0];
        __syncwarp();
    }
}

// ---------------- launch ----------------
extern "C" void kernel_launch(void* const* d_in, const int* in_sizes, int n_in,
                              void* d_out, int out_size)
{
    const float* x       = (const float*)d_in[0];
    const float* w_ih1_f = (const float*)d_in[1];
    const float* w_hh1_f = (const float*)d_in[2];
    const float* b_ih1_f = (const float*)d_in[3];
    const float* b_hh1_f = (const float*)d_in[4];
    const float* w_ih1_b = (const float*)d_in[5];
    const float* w_hh1_b = (const float*)d_in[6];
    const float* b_ih1_b = (const float*)d_in[7];
    const float* b_hh1_b = (const float*)d_in[8];
    const float* w_ih2_f = (const float*)d_in[9];
    const float* w_hh2_f = (const float*)d_in[10];
    const float* b_ih2_f = (const float*)d_in[11];
    const float* b_hh2_f = (const float*)d_in[12];
    const float* w_ih2_b = (const float*)d_in[13];
    const float* w_hh2_b = (const float*)d_in[14];
    const float* b_ih2_b = (const float*)d_in[15];
    const float* b_hh2_b = (const float*)d_in[16];
    const float* fc1_w   = (const float*)d_in[17];
    const float* fc1_b   = (const float*)d_in[18];
    const float* fc2_w   = (const float*)d_in[19];
    const float* fc2_b   = (const float*)d_in[20];
    float* y = (float*)d_out;

    float *xpf, *xpb, *o2;
    __half *xhi, *xlo, *ohi, *olo, *whi, *whhhi;
    cudaGetSymbolAddress((void**)&xpf, g_xpf);
    cudaGetSymbolAddress((void**)&xpb, g_xpb);
    cudaGetSymbolAddress((void**)&o2,  g_o2);
    cudaGetSymbolAddress((void**)&xhi, g_xhi);
    cudaGetSymbolAddress((void**)&xlo, g_xlo);
    cudaGetSymbolAddress((void**)&ohi, g_ohi);
    cudaGetSymbolAddress((void**)&olo, g_olo);
    cudaGetSymbolAddress((void**)&whi, g_whi);
    cudaGetSymbolAddress((void**)&whhhi, g_whhhi);

    const int poolSmem = (64 * W1PITCH + 8 * 512) * 4;
    cudaFuncSetAttribute(pool_fc,  cudaFuncAttributeMaxDynamicSharedMemorySize, poolSmem);
    cudaFuncSetAttribute(gemm_mma, cudaFuncAttributeMaxDynamicSharedMemorySize, GEMMSMEM);
    cudaFuncSetAttribute(lstm_rec_mma, cudaFuncAttributeMaxDynamicSharedMemorySize, RECSMEM);

    const size_t WSLOT = (size_t)GG * K2P;      // w_ih slot stride (layer2-size)
    const size_t HSLOT = (size_t)GG * HH;
    dim3 gemmGrid(16, MM / 128);                 // fused f+b, N-tile 64
    dim3 recGrid(BB / 64, 2);

    // 0) x split, 1-2) layer-1 w_ih hi (contiguous, stride GG*K1P), 3) w_hh1_f
    convert_split<<<16384, 256>>>(x, xhi, xlo, MM, II, K1P);
    convert_h<<<512, 256>>>(w_ih1_f, whi,                    GG, II, K1P);
    convert_h<<<512, 256>>>(w_ih1_b, whi + (size_t)GG * K1P, GG, II, K1P);
    convert_h<<<256, 256>>>(w_hh1_f, whhhi + 0 * HSLOT, GG, HH, HH);

    // 4) layer 1 xproj (fused f+b) — launch index 4 is the ncu capture target
    gemm_mma<<<gemmGrid, 256, GEMMSMEM>>>(xhi, xlo, whi, K1P, 3,
                                          b_ih1_f, b_hh1_f, b_ih1_b, b_hh1_b,
                                          xpf, xpb);

    // 5-9) remaining weight conversions
    convert_h<<<256, 256>>>(w_hh1_b, whhhi + 1 * HSLOT, GG, HH, HH);
    convert_h<<<512, 256>>>(w_ih2_f, whi + 2 * WSLOT, GG, 2 * HH, K2P);
    convert_h<<<512, 256>>>(w_ih2_b, whi + 3 * WSLOT, GG, 2 * HH, K2P);
    convert_h<<<256, 256>>>(w_hh2_f, whhhi + 2 * HSLOT, GG, HH, HH);
    convert_h<<<256, 256>>>(w_hh2_b, whhhi + 3 * HSLOT, GG, HH, HH);

    // 10) layer 1 recurrence -> fp16 hi/lo for layer-2 GEMM A
    lstm_rec_mma<<<recGrid, 256, RECSMEM>>>(xpf, xpb, whhhi,
                                            (float*)nullptr, ohi, olo);

    // 11) layer 2 xproj (fused f+b, K=256)
    gemm_mma<<<gemmGrid, 256, GEMMSMEM>>>(ohi, olo, whi + 2 * WSLOT, K2P, 4,
                                          b_ih2_f, b_hh2_f, b_ih2_b, b_hh2_b,
                                          xpf, xpb);

    // 12) layer 2 recurrence -> fp32 output
    lstm_rec_mma<<<recGrid, 256, RECSMEM>>>(xpf, xpb, whhhi + 2 * HSLOT,
                                            o2, (__half*)nullptr, (__half*)nullptr);

    // 13) pool + FC head
    pool_fc<<<256, 256, poolSmem>>>(o2, fc1_w, fc1_b, fc2_w, fc2_b, y, 8);
}

// round 11
// speedup vs baseline: 1.4487x; 1.4487x over previous
#include <cuda_runtime.h>
#include <cuda_fp16.h>
#include <cstdint>

// Problem constants
#define BB 16384
#define TT 10
#define II 184
#define HH 128
#define GG 512            // 4*H
#define MM (BB*TT)        // 163840 rows for xproj GEMMs
#define K1P 192           // layer-1 K padded (184 -> 192)
#define K2P 256           // layer-2 K

// ---------------- device scratch (no allocations allowed) ----------------
__device__ float g_xpf[(size_t)MM * GG];
__device__ float g_xpb[(size_t)MM * GG];
__device__ float g_o2 [(size_t)MM * 2 * HH];
__device__ __half g_xhi[(size_t)MM * K1P];          // x split hi (fp16)
__device__ __half g_xlo[(size_t)MM * K1P];          // x split lo
__device__ __half g_ohi[(size_t)MM * K2P];          // layer1 out split hi
__device__ __half g_olo[(size_t)MM * K2P];          // layer1 out split lo
__device__ __half g_whi[4 * (size_t)GG * K2P];      // w_ih hi only (4 slots)
__device__ __half g_whhhi[4 * (size_t)GG * HH];     // w_hh hi only (4 slots)

// ---------------- small PTX helpers ----------------
__device__ __forceinline__ uint32_t smem_u32(const void* p) {
    uint32_t a;
    asm("{ .reg .u64 t; cvta.to.shared.u64 t, %1; cvt.u32.u64 %0, t; }" : "=r"(a) : "l"(p));
    return a;
}
__device__ __forceinline__ void ldm_x4(uint32_t& r0, uint32_t& r1, uint32_t& r2, uint32_t& r3,
                                       uint32_t addr) {
    asm volatile("ldmatrix.sync.aligned.m8n8.x4.shared.b16 {%0,%1,%2,%3}, [%4];"
                 : "=r"(r0), "=r"(r1), "=r"(r2), "=r"(r3) : "r"(addr));
}
__device__ __forceinline__ void mma_f16(float* c, const uint32_t* a, const uint32_t* b) {
    asm volatile(
        "mma.sync.aligned.m16n8k16.row.col.f32.f16.f16.f32 "
        "{%0,%1,%2,%3}, {%4,%5,%6,%7}, {%8,%9}, {%0,%1,%2,%3};"
        : "+f"(c[0]), "+f"(c[1]), "+f"(c[2]), "+f"(c[3])
        : "r"(a[0]), "r"(a[1]), "r"(a[2]), "r"(a[3]), "r"(b[0]), "r"(b[1]));
}
__device__ __forceinline__ void cp16(uint32_t dst, const void* src) {
    asm volatile("cp.async.cg.shared.global [%0], [%1], 16;" :: "r"(dst), "l"(src));
}
__device__ __forceinline__ void cp_commit() {
    asm volatile("cp.async.commit_group;" ::: "memory");
}
__device__ __forceinline__ void cp_wait1() {
    asm volatile("cp.async.wait_group 1;" ::: "memory");
}
__device__ __forceinline__ void cp_wait0() {
    asm volatile("cp.async.wait_group 0;" ::: "memory");
}

// ---------------- activation helpers ----------------
__device__ __forceinline__ float fsig(float x) {
    return __fdividef(1.0f, 1.0f + __expf(-x));
}
__device__ __forceinline__ float ftanh(float x) {
    x = fminf(x, 15.0f);
    float e = __expf(2.0f * x);
    return __fdividef(e - 1.0f, e + 1.0f);
}

// ---------------- fp32 -> fp16 hi/lo split (with K zero-padding) ----------
__global__ void convert_split(const float* __restrict__ src,
                              __half* __restrict__ dhi,
                              __half* __restrict__ dlo,
                              unsigned rows, unsigned Ksrc, unsigned Kpad)
{
    unsigned total = rows * Kpad;
    for (unsigned idx = blockIdx.x * blockDim.x + threadIdx.x; idx < total;
         idx += gridDim.x * blockDim.x) {
        unsigned row = idx / Kpad;
        unsigned k = idx - row * Kpad;
        float v = (k < Ksrc) ? src[(size_t)row * Ksrc + k] : 0.0f;
        __half h = __float2half_rn(v);
        dhi[idx] = h;
        dlo[idx] = __float2half_rn(v - __half2float(h));
    }
}

// ---------------- fp32 -> fp16 hi only (weights) --------------------------
__global__ void convert_h(const float* __restrict__ src,
                          __half* __restrict__ dhi,
                          unsigned rows, unsigned Ksrc, unsigned Kpad)
{
    unsigned total = rows * Kpad;
    for (unsigned idx = blockIdx.x * blockDim.x + threadIdx.x; idx < total;
         idx += gridDim.x * blockDim.x) {
        unsigned row = idx / Kpad;
        unsigned k = idx - row * Kpad;
        float v = (k < Ksrc) ? src[(size_t)row * Ksrc + k] : 0.0f;
        dhi[idx] = __float2half_rn(v);
    }
}

// ---------------- split-fp16 2-term GEMM, cp.async 2-stage pipeline -------
// R9 proven version: CTA tile 128x128, NO reg cap.
// FUSED f+b: grid = (8, M/128). blockIdx.x>>2 = direction, &3 = N block.
#define PIT 72
#define PITB 144
#define ATILEB (128 * PITB)            // 18432 bytes per operand tile
#define GSTAGEB (3 * ATILEB)           // 55296 bytes per pipeline stage
#define GEMMSMEM (2 * GSTAGEB + 512)   // 111104
__global__ __launch_bounds__(256) void gemm_mma(
    const __half* __restrict__ a_hi, const __half* __restrict__ a_lo,
    const __half* __restrict__ w_base,          // 2 slots, stride GG*Kpad
    int Kpad, int nchunks,
    const float* __restrict__ b1f, const float* __restrict__ b2f,
    const float* __restrict__ b1b, const float* __restrict__ b2b,
    float* __restrict__ Cf, float* __restrict__ Cb)
{
    extern __shared__ __half sm[];
    const uint32_t sb0 = smem_u32(sm);
    float* sbias = (float*)((char*)sm + 2 * GSTAGEB);

    const int tid  = threadIdx.x;
    const int wid  = tid >> 5;
    const int lane = tid & 31;
    const int wm   = wid & 3;
    const int wn   = wid >> 2;
    const int dsel = blockIdx.x >> 2;            // 0 = fwd, 1 = bwd
    const int n0   = (blockIdx.x & 3) * 128;     // N block
    const int m0   = blockIdx.y * 128;

    const __half* w_hi = w_base + (size_t)dsel * GG * Kpad;
    const float*  b1   = dsel ? b1b : b1f;
    const float*  b2   = dsel ? b2b : b2f;
    float*        C    = dsel ? Cb  : Cf;

    if (tid < 128) sbias[tid] = b1[n0 + tid] + b2[n0 + tid];

    const uint32_t aoff = (uint32_t)(lane & 15) * PITB + (uint32_t)(lane >> 4) * 16;
    const uint32_t boff = ((uint32_t)((lane & 7) + ((lane >> 4) << 3))) * PITB
                        + (uint32_t)((lane >> 3) & 1) * 16;

    // issue cp.async for chunk c into stage st (3 tiles: Ahi, Alo, Bhi)
    auto load_chunk = [&](int c, int st) {
        const int kb = c * 64;
        const uint32_t base = sb0 + (uint32_t)st * GSTAGEB;
#pragma unroll
        for (int i = 0; i < 4; i++) {
            int idx = tid + i * 256;          // 0..1023
            int row = idx >> 3, seg = idx & 7;
            uint32_t d = base + (uint32_t)row * PITB + (uint32_t)seg * 16;
            cp16(d,              a_hi + (size_t)(m0 + row) * Kpad + kb + seg * 8);
            cp16(d + ATILEB,     a_lo + (size_t)(m0 + row) * Kpad + kb + seg * 8);
            cp16(d + 2 * ATILEB, w_hi + (size_t)(n0 + row) * Kpad + kb + seg * 8);
        }
        cp_commit();
    };

    float acc[2][8][4];
#pragma unroll
    for (int mt = 0; mt < 2; mt++)
#pragma unroll
        for (int nt = 0; nt < 8; nt++)
#pragma unroll
            for (int q = 0; q < 4; q++) acc[mt][nt][q] = 0.0f;

    load_chunk(0, 0);
    if (nchunks > 1) load_chunk(1, 1);

    for (int c = 0; c < nchunks; c++) {
        if (c < nchunks - 1) cp_wait1(); else cp_wait0();
        __syncthreads();

        const uint32_t stg = sb0 + (uint32_t)(c & 1) * GSTAGEB;
        const uint32_t sAh = stg, sAl = stg + ATILEB, sBh = stg + 2 * ATILEB;

#pragma unroll
        for (int ks = 0; ks < 4; ks++) {
            const uint32_t kbyte = (uint32_t)(ks * 32);

            uint32_t ah[2][4], al[2][4];
#pragma unroll
            for (int mt = 0; mt < 2; mt++) {
                uint32_t rbase = (uint32_t)(wm * 32 + mt * 16) * PITB + aoff + kbyte;
                ldm_x4(ah[mt][0], ah[mt][1], ah[mt][2], ah[mt][3], sAh + rbase);
                ldm_x4(al[mt][0], al[mt][1], al[mt][2], al[mt][3], sAl + rbase);
            }

#pragma unroll
            for (int half = 0; half < 2; half++) {
                uint32_t bh[4][2];
#pragma unroll
                for (int p = 0; p < 2; p++) {
                    uint32_t nb = (uint32_t)(wn * 64 + half * 32 + p * 16) * PITB + boff + kbyte;
                    ldm_x4(bh[2*p][0], bh[2*p][1], bh[2*p+1][0], bh[2*p+1][1], sBh + nb);
                }
#pragma unroll
                for (int mt = 0; mt < 2; mt++)
#pragma unroll
                    for (int nt = 0; nt < 4; nt++) {
                        float* cc = acc[mt][half * 4 + nt];
                        mma_f16(cc, ah[mt], bh[nt]);   // hi * Whi
                        mma_f16(cc, al[mt], bh[nt]);   // lo * Whi
                    }
            }
        }
        __syncthreads();
        if (c + 2 < nchunks) load_chunk(c + 2, c & 1);
    }

    const int g = lane >> 2, t = lane & 3;
#pragma unroll
    for (int mt = 0; mt < 2; mt++) {
        const int row0 = m0 + wm * 32 + mt * 16 + g;
#pragma unroll
        for (int nt = 0; nt < 8; nt++) {
            const int cl = wn * 64 + nt * 8 + 2 * t;
            float2 v0, v1;
            v0.x = acc[mt][nt][0] + sbias[cl];
            v0.y = acc[mt][nt][1] + sbias[cl + 1];
            v1.x = acc[mt][nt][2] + sbias[cl];
            v1.y = acc[mt][nt][3] + sbias[cl + 1];
            *(float2*)&C[(size_t)row0 * GG + n0 + cl] = v0;
            *(float2*)&C[(size_t)(row0 + 8) * GG + n0 + cl] = v1;
        }
    }
}

// ---------------- tensorized bidirectional LSTM recurrence ----------------
// 64 batch rows/CTA, 1 direction. Full W_hh (hi fp16) resident in SMEM.
// h kept HI-ONLY in smem (R10-validated: rel_err 2.20e-4) -> half the
// MMAs/ldmatrix of the hi/lo variant. gmem ohi/olo stays exact hi/lo.
#define HPITB 272                         // smem row pitch bytes (136 halves)
#define WREGB (512 * HPITB)               // 139264 bytes: whole W_hh hi
#define RECSMEM (WREGB + 64 * HPITB)      // +17408 = 156672
__global__ __launch_bounds__(256, 1) void lstm_rec_mma(
    const float* __restrict__ xp_f, const float* __restrict__ xp_b,
    const __half* __restrict__ whh_hi_base,   // 2 dirs, each [512][128]
    float* __restrict__ out32,
    __half* __restrict__ ohi, __half* __restrict__ olo)
{
    extern __shared__ __half smr[];
    const uint32_t sb = smem_u32(smr);
    const uint32_t wB  = sb;
    const uint32_t hHi = sb + WREGB;

    const int dir = blockIdx.y;
    const float* xp = dir ? xp_b : xp_f;
    const __half* whh_hi = whh_hi_base + (size_t)dir * GG * HH;

    const int tid  = threadIdx.x;
    const int wid  = tid >> 5;
    const int lane = tid & 31;
    const int wm   = wid & 1;        // M half (32 rows)
    const int wn   = wid >> 1;       // 0..3 -> hidden col group of 32
    const int b0   = blockIdx.x * 64;
    const int g4   = lane >> 2;
    const int t4   = lane & 3;

    const uint32_t aoff = (uint32_t)(lane & 15) * HPITB + (uint32_t)(lane >> 4) * 16;
    const uint32_t boff = ((uint32_t)((lane & 7) + ((lane >> 4) << 3))) * HPITB
                        + (uint32_t)((lane >> 3) & 1) * 16;

    // load the ENTIRE W_hh (hi) once: 512 rows x 256B -> 8192 cp16
#pragma unroll
    for (int i = 0; i < 32; i++) {
        int idx = tid + i * 256;            // 0..8191
        int row = idx >> 4, seg = idx & 15;
        cp16(wB + (uint32_t)row * HPITB + (uint32_t)seg * 16,
             whh_hi + (size_t)row * HH + seg * 8);
    }
    cp_commit();

    // zero h (hi only, 64*272 bytes)
    for (int i = tid; i < (64 * HPITB) / 4; i += 256)
        *(uint32_t*)((char*)smr + WREGB + i * 4) = 0u;
    cp_wait0();
    __syncthreads();

    float cst[2][4][4];
#pragma unroll
    for (int mt = 0; mt < 2; mt++)
#pragma unroll
        for (int nt = 0; nt < 4; nt++)
#pragma unroll
            for (int e = 0; e < 4; e++) cst[mt][nt][e] = 0.0f;

    float acc[4][2][4][4];

    for (int s = 0; s < TT; s++) {
        const int t = dir ? (TT - 1 - s) : s;

        // init accumulators from xproj (biases pre-folded by GEMM epilogue)
#pragma unroll
        for (int gate = 0; gate < 4; gate++)
#pragma unroll
            for (int mt = 0; mt < 2; mt++) {
                const int r = wm * 32 + mt * 16 + g4;
                const size_t base0 = ((size_t)(b0 + r) * TT + t) * GG + gate * 128;
                const size_t base1 = ((size_t)(b0 + r + 8) * TT + t) * GG + gate * 128;
#pragma unroll
                for (int nt = 0; nt < 4; nt++) {
                    const int j = wn * 32 + nt * 8 + 2 * t4;
                    float2 v0 = *(const float2*)&xp[base0 + j];
                    float2 v1 = *(const float2*)&xp[base1 + j];
                    acc[gate][mt][nt][0] = v0.x; acc[gate][mt][nt][1] = v0.y;
                    acc[gate][mt][nt][2] = v1.x; acc[gate][mt][nt][3] = v1.y;
                }
            }

        // gates += h_prev @ W_hh^T (h hi only)
#pragma unroll
        for (int ks = 0; ks < 8; ks++) {
            const uint32_t kb = (uint32_t)(ks * 32);
            uint32_t ah[2][4];
#pragma unroll
            for (int mt = 0; mt < 2; mt++) {
                uint32_t rb = (uint32_t)(wm * 32 + mt * 16) * HPITB + aoff + kb;
                ldm_x4(ah[mt][0], ah[mt][1], ah[mt][2], ah[mt][3], hHi + rb);
            }
#pragma unroll
            for (int gate = 0; gate < 4; gate++) {
                uint32_t bh[4][2];
#pragma unroll
                for (int p = 0; p < 2; p++) {
                    uint32_t nb = (uint32_t)(gate * 128 + wn * 32 + p * 16) * HPITB + boff + kb;
                    ldm_x4(bh[2*p][0], bh[2*p][1], bh[2*p+1][0], bh[2*p+1][1], wB + nb);
                }
#pragma unroll
                for (int mt = 0; mt < 2; mt++)
#pragma unroll
                    for (int nt = 0; nt < 4; nt++)
                        mma_f16(acc[gate][mt][nt], ah[mt], bh[nt]);
            }
        }
        __syncthreads();   // all h reads complete before overwrite

        // activations + cell update + h emit
#pragma unroll
        for (int mt = 0; mt < 2; mt++) {
            const int r = wm * 32 + mt * 16 + g4;
#pragma unroll
            for (int nt = 0; nt < 4; nt++) {
                const int j = wn * 32 + nt * 8 + 2 * t4;
                float hv[4];
#pragma unroll
                for (int e = 0; e < 4; e++) {
                    float ig = fsig(acc[0][mt][nt][e]);
                    float fg = fsig(acc[1][mt][nt][e]);
                    float gg = ftanh(acc[2][mt][nt][e]);
                    float og = fsig(acc[3][mt][nt][e]);
                    float cc = fg * cst[mt][nt][e] + ig * gg;
                    cst[mt][nt][e] = cc;
                    hv[e] = og * ftanh(cc);
                }
                __half h0x = __float2half_rn(hv[0]);
                __half h0y = __float2half_rn(hv[1]);
                __half h1x = __float2half_rn(hv[2]);
                __half h1y = __float2half_rn(hv[3]);
                __half2 hp0 = __halves2half2(h0x, h0y);
                __half2 hp1 = __halves2half2(h1x, h1y);
                uint32_t uh0 = *reinterpret_cast<uint32_t*>(&hp0);
                uint32_t uh1 = *reinterpret_cast<uint32_t*>(&hp1);

                // smem h (hi only) for next step
                *(uint32_t*)((char*)smr + WREGB + r * HPITB + j * 2) = uh0;
                *(uint32_t*)((char*)smr + WREGB + (r + 8) * HPITB + j * 2) = uh1;

                // gmem output
                const size_t ob0 = ((size_t)(b0 + r) * TT + t) * (2 * HH) + dir * HH + j;
                const size_t ob1 = ((size_t)(b0 + r + 8) * TT + t) * (2 * HH) + dir * HH + j;
                if (out32) {
                    *(float2*)&out32[ob0] = make_float2(hv[0], hv[1]);
                    *(float2*)&out32[ob1] = make_float2(hv[2], hv[3]);
                } else {
                    __half2 lp0 = __halves2half2(__float2half_rn(hv[0] - __half2float(h0x)),
                                                 __float2half_rn(hv[1] - __half2float(h0y)));
                    __half2 lp1 = __halves2half2(__float2half_rn(hv[2] - __half2float(h1x)),
                                                 __float2half_rn(hv[3] - __half2float(h1y)));
                    *(uint32_t*)&ohi[ob0] = uh0;
                    *(uint32_t*)&ohi[ob1] = uh1;
                    *(uint32_t*)&olo[ob0] = *reinterpret_cast<uint32_t*>(&lp0);
                    *(uint32_t*)&olo[ob1] = *reinterpret_cast<uint32_t*>(&lp1);
                }
            }
        }
        __syncthreads();   // h writes visible before next step's reads
    }
}

// ---------------- fused maxpool(T) + FC(512->64) + ReLU + FC(64->1) -------
#define W1PITCH 517
__global__ __launch_bounds__(256) void pool_fc(
    const float* __restrict__ o2,
    const float* __restrict__ fc1w, const float* __restrict__ fc1b,
    const float* __restrict__ fc2w, const float* __restrict__ fc2b,
    float* __restrict__ y, int rows_per_warp)
{
    extern __shared__ float smf[];
    float* w1    = smf;
    float* feats = smf + 64 * W1PITCH;

    for (int i = threadIdx.x; i < 64 * 512; i += 256) {
        int j = i >> 9, f = i & 511;
        w1[j * W1PITCH + f] = fc1w[i];
    }
    __syncthreads();

    const int wid  = threadIdx.x >> 5;
    const int lane = threadIdx.x & 31;
    float* myfeat = feats + wid * 512;

    for (int it = 0; it < rows_per_warp; it++) {
        int b = blockIdx.x * (8 * rows_per_warp) + it * 8 + wid;

#pragma unroll
        for (int q = 0; q < 8; q++) {
            int cc = lane + q * 32;
            float m0 = -3.4e38f, m1 = -3.4e38f;
#pragma unroll
            for (int t = 0; t < 5; t++)
                m0 = fmaxf(m0, o2[((size_t)b * TT + t) * (2 * HH) + cc]);
#pragma unroll
            for (int t = 5; t < 10; t++)
                m1 = fmaxf(m1, o2[((size_t)b * TT + t) * (2 * HH) + cc]);
            myfeat[cc * 2 + 0] = m0;
            myfeat[cc * 2 + 1] = m1;
        }
        __syncwarp();

        float a0 = fc1b[lane];
        float a1 = fc1b[lane + 32];
        const float* wr0 = &w1[lane * W1PITCH];
        const float* wr1 = &w1[(lane + 32) * W1PITCH];
#pragma unroll 8
        for (int f = 0; f < 512; f++) {
            float v = myfeat[f];
            a0 += v * wr0[f];
            a1 += v * wr1[f];
        }
        a0 = fmaxf(a0, 0.0f);
        a1 = fmaxf(a1, 0.0f);

        float p = a0 * fc2w[lane] + a1 * fc2w[lane + 32];
#pragma unroll
        for (int off = 16; off; off >>= 1)
            p += __shfl_down_sync(0xffffffffu, p, off);
        if (lane == 0) y[b] = p + fc2b[0];
        __syncwarp();
    }
}

// ---------------- launch ----------------
extern "C" void kernel_launch(void* const* d_in, const int* in_sizes, int n_in,
                              void* d_out, int out_size)
{
    const float* x       = (const float*)d_in[0];
    const float* w_ih1_f = (const float*)d_in[1];
    const float* w_hh1_f = (const float*)d_in[2];
    const float* b_ih1_f = (const float*)d_in[3];
    const float* b_hh1_f = (const float*)d_in[4];
    const float* w_ih1_b = (const float*)d_in[5];
    const float* w_hh1_b = (const float*)d_in[6];
    const float* b_ih1_b = (const float*)d_in[7];
    const float* b_hh1_b = (const float*)d_in[8];
    const float* w_ih2_f = (const float*)d_in[9];
    const float* w_hh2_f = (const float*)d_in[10];
    const float* b_ih2_f = (const float*)d_in[11];
    const float* b_hh2_f = (const float*)d_in[12];
    const float* w_ih2_b = (const float*)d_in[13];
    const float* w_hh2_b = (const float*)d_in[14];
    const float* b_ih2_b = (const float*)d_in[15];
    const float* b_hh2_b = (const float*)d_in[16];
    const float* fc1_w   = (const float*)d_in[17];
    const float* fc1_b   = (const float*)d_in[18];
    const float* fc2_w   = (const float*)d_in[19];
    const float* fc2_b   = (const float*)d_in[20];
    float* y = (float*)d_out;

    float *xpf, *xpb, *o2;
    __half *xhi, *xlo, *ohi, *olo, *whi, *whhhi;
    cudaGetSymbolAddress((void**)&xpf, g_xpf);
    cudaGetSymbolAddress((void**)&xpb, g_xpb);
    cudaGetSymbolAddress((void**)&o2,  g_o2);
    cudaGetSymbolAddress((void**)&xhi, g_xhi);
    cudaGetSymbolAddress((void**)&xlo, g_xlo);
    cudaGetSymbolAddress((void**)&ohi, g_ohi);
    cudaGetSymbolAddress((void**)&olo, g_olo);
    cudaGetSymbolAddress((void**)&whi, g_whi);
    cudaGetSymbolAddress((void**)&whhhi, g_whhhi);

    const int poolSmem = (64 * W1PITCH + 8 * 512) * 4;
    cudaFuncSetAttribute(pool_fc,  cudaFuncAttributeMaxDynamicSharedMemorySize, poolSmem);
    cudaFuncSetAttribute(gemm_mma, cudaFuncAttributeMaxDynamicSharedMemorySize, GEMMSMEM);
    cudaFuncSetAttribute(lstm_rec_mma, cudaFuncAttributeMaxDynamicSharedMemorySize, RECSMEM);

    const size_t WSLOT = (size_t)GG * K2P;      // w_ih slot stride (layer2-size)
    const size_t HSLOT = (size_t)GG * HH;
    dim3 gemmGrid(8, MM / 128);                  // fused f+b, N-tile 128
    dim3 recGrid(BB / 64, 2);

    // 0) x split, 1-2) layer-1 w_ih hi (contiguous, stride GG*K1P), 3) w_hh1_f
    convert_split<<<16384, 256>>>(x, xhi, xlo, MM, II, K1P);
    convert_h<<<512, 256>>>(w_ih1_f, whi,                    GG, II, K1P);
    convert_h<<<512, 256>>>(w_ih1_b, whi + (size_t)GG * K1P, GG, II, K1P);
    convert_h<<<256, 256>>>(w_hh1_f, whhhi + 0 * HSLOT, GG, HH, HH);

    // 4) layer 1 xproj (fused f+b) — launch index 4 is the ncu capture target
    gemm_mma<<<gemmGrid, 256, GEMMSMEM>>>(xhi, xlo, whi, K1P, 3,
                                          b_ih1_f, b_hh1_f, b_ih1_b, b_hh1_b,
                                          xpf, xpb);

    // 5-9) remaining weight conversions
    convert_h<<<256, 256>>>(w_hh1_b, whhhi + 1 * HSLOT, GG, HH, HH);
    convert_h<<<512, 256>>>(w_ih2_f, whi + 2 * WSLOT, GG, 2 * HH, K2P);
    convert_h<<<512, 256>>>(w_ih2_b, whi + 3 * WSLOT, GG, 2 * HH, K2P);
    convert_h<<<256, 256>>>(w_hh2_f, whhhi + 2 * HSLOT, GG, HH, HH);
    convert_h<<<256, 256>>>(w_hh2_b, whhhi + 3 * HSLOT, GG, HH, HH);

    // 10) layer 1 recurrence -> fp16 hi/lo for layer-2 GEMM A
    lstm_rec_mma<<<recGrid, 256, RECSMEM>>>(xpf, xpb, whhhi,
                                            (float*)nullptr, ohi, olo);

    // 11) layer 2 xproj (fused f+b, K=256)
    gemm_mma<<<gemmGrid, 256, GEMMSMEM>>>(ohi, olo, whi + 2 * WSLOT, K2P, 4,
                                          b_ih2_f, b_hh2_f, b_ih2_b, b_hh2_b,
                                          xpf, xpb);

    // 12) layer 2 recurrence -> fp32 output
    lstm_rec_mma<<<recGrid, 256, RECSMEM>>>(xpf, xpb, whhhi + 2 * HSLOT,
                                            o2, (__half*)nullptr, (__half*)nullptr);

    // 13) pool + FC head
    pool_fc<<<256, 256, poolSmem>>>(o2, fc1_w, fc1_b, fc2_w, fc2_b, y, 8);
}